// round 3
// baseline (speedup 1.0000x reference)
#include <cuda_runtime.h>
#include <cuda_bf16.h>
#include <math.h>

#define NB   16
#define CH   64
#define HH   128
#define WW   128
#define PLANE (HH*WW)          // 16384
#define GK2  72
#define BN_EPS 1e-5f

__device__ float g_pooled[NB * CH];
__device__ float g_f[NB * GK2];
__device__ int   g_cnt[NB];            // zero-init at load; self-resetting

// ---------------------------------------------------------------------------
// Kernel 1: avg-pool each plane; the LAST CTA of each image also computes the
// 72 BN+softmax weights for that image (removes the middle kernel launch).
// Triggers PDL immediately so the decouple kernel can start staging early.
// ---------------------------------------------------------------------------
__global__ void __launch_bounds__(256) pool_kernel(const float* __restrict__ x,
                                                   const float* __restrict__ conv_w,
                                                   const float* __restrict__ gamma,
                                                   const float* __restrict__ beta,
                                                   const float* __restrict__ mean,
                                                   const float* __restrict__ var) {
    cudaTriggerProgrammaticLaunchCompletion();

    const int p = blockIdx.x;                     // n*CH + c
    const int n = p >> 6;
    const float4* xp = (const float4*)(x + (size_t)p * PLANE);
    float s = 0.f;
    #pragma unroll
    for (int j = 0; j < 16; j++) {
        float4 v = xp[threadIdx.x + j * 256];
        s += (v.x + v.y) + (v.z + v.w);
    }
    #pragma unroll
    for (int o = 16; o > 0; o >>= 1) s += __shfl_xor_sync(0xffffffffu, s, o);

    __shared__ float ws[8];
    __shared__ int   is_last;
    __shared__ float sf[GK2];

    if ((threadIdx.x & 31) == 0) ws[threadIdx.x >> 5] = s;
    __syncthreads();
    if (threadIdx.x < 8) {
        s = ws[threadIdx.x];
        #pragma unroll
        for (int o = 4; o > 0; o >>= 1) s += __shfl_xor_sync(0x000000ffu, s, o);
        if (threadIdx.x == 0) {
            g_pooled[p] = s * (1.f / (float)PLANE);
            __threadfence();
            int old = atomicAdd(&g_cnt[n], 1);
            is_last = (old == CH - 1);
        }
    }
    __syncthreads();
    if (!is_last) return;

    __threadfence();                              // acquire all g_pooled[n*64..]
    const int j = threadIdx.x;                    // 0..255, use 0..71
    if (j < GK2) {
        const float* pn = g_pooled + n * CH;
        const float* wj = conv_w + j * CH;
        float acc = 0.f;
        #pragma unroll
        for (int c = 0; c < CH; c++) acc = fmaf(pn[c], wj[c], acc);
        acc = gamma[j] * (acc - mean[j]) * rsqrtf(var[j] + BN_EPS) + beta[j];
        sf[j] = acc;
    }
    __syncthreads();
    if (j < GK2) {
        const int g = j / 9;
        const float* sg = sf + g * 9;
        float m = sg[0];
        #pragma unroll
        for (int i = 1; i < 9; i++) m = fmaxf(m, sg[i]);
        float sum = 0.f;
        #pragma unroll
        for (int i = 0; i < 9; i++) sum += __expf(sg[i] - m);
        g_f[n * GK2 + j] = __expf(sf[j] - m) / sum;
    }
    if (j == 0) g_cnt[n] = 0;                     // reset for next graph replay
}

// ---------------------------------------------------------------------------
// Kernel 2: half-plane tiles (64 rows + staged 66-row halo, reflection baked
// into staging). Warp-per-row, conflict-free LDS.128 + lane shuffles.
// PDL: stages x first, then waits for pool, then reads weights.
// ---------------------------------------------------------------------------
__device__ __forceinline__ void row_taps(float4 v, int lane, float wl, float wc, float wr,
                                         float acc[4]) {
    float left  = __shfl_up_sync(0xffffffffu, v.w, 1);
    float right = __shfl_down_sync(0xffffffffu, v.x, 1);
    if (lane == 0)  left  = v.y;   // reflect x[-1] -> x[1]
    if (lane == 31) right = v.z;   // reflect x[128] -> x[126]
    acc[0] = fmaf(left, wl, fmaf(v.x, wc, fmaf(v.y, wr, acc[0])));
    acc[1] = fmaf(v.x,  wl, fmaf(v.y, wc, fmaf(v.z, wr, acc[1])));
    acc[2] = fmaf(v.y,  wl, fmaf(v.z, wc, fmaf(v.w, wr, acc[2])));
    acc[3] = fmaf(v.z,  wl, fmaf(v.w, wc, fmaf(right, wr, acc[3])));
}

__global__ void __launch_bounds__(256) decouple_kernel(const float* __restrict__ x,
                                                       float* __restrict__ out) {
    extern __shared__ float tile[];               // 66 rows * 128 = 33792 B
    const int b = blockIdx.x;
    const int p = b >> 1;                         // plane
    const int start = (b & 1) * 64;               // first output row
    const size_t base = (size_t)p * PLANE;
    const float4* xin = (const float4*)(x + base);
    float4* t4 = (float4*)tile;

    // stage rows start-1 .. start+64 with top/bottom reflection applied
    for (int i = threadIdx.x; i < 66 * 32; i += 256) {
        int gr = start + (i >> 5) - 1;
        gr = (gr < 0) ? 1 : ((gr > HH - 1) ? HH - 2 : gr);
        t4[i] = xin[gr * 32 + (i & 31)];
    }
    __syncthreads();

    cudaGridDependencySynchronize();              // pool (and weights) done

    const int n = p >> 6;
    const int g = (p & 63) >> 3;
    const float* fw = g_f + n * GK2 + g * 9;
    float w[9];
    #pragma unroll
    for (int k = 0; k < 9; k++) w[k] = fw[k];

    float4* olow = (float4*)(out + base);
    float4* ores = (float4*)(out + (size_t)NB * CH * PLANE + base);

    const int lane = threadIdx.x & 31;
    const int warp = threadIdx.x >> 5;            // 0..7

    #pragma unroll
    for (int iter = 0; iter < 8; iter++) {
        const int tr = iter * 8 + warp + 1;       // tile row 1..64 (center)
        float4 va = t4[(tr - 1) * 32 + lane];
        float4 vb = t4[ tr      * 32 + lane];
        float4 vc = t4[(tr + 1) * 32 + lane];

        float acc[4] = {0.f, 0.f, 0.f, 0.f};
        row_taps(va, lane, w[0], w[1], w[2], acc);
        row_taps(vb, lane, w[3], w[4], w[5], acc);
        row_taps(vc, lane, w[6], w[7], w[8], acc);

        float4 L = make_float4(acc[0], acc[1], acc[2], acc[3]);
        float4 R = make_float4(vb.x - acc[0], vb.y - acc[1],
                               vb.z - acc[2], vb.w - acc[3]);
        const int oi = (start + tr - 1) * 32 + lane;
        __stcs(olow + oi, L);
        __stcs(ores + oi, R);
    }
}

// ---------------------------------------------------------------------------
extern "C" void kernel_launch(void* const* d_in, const int* in_sizes, int n_in,
                              void* d_out, int out_size) {
    const float* x      = (const float*)d_in[0];
    const float* conv_w = (const float*)d_in[1];
    const float* gamma  = (const float*)d_in[2];
    const float* beta   = (const float*)d_in[3];
    const float* mean   = (const float*)d_in[4];
    const float* var    = (const float*)d_in[5];
    float* out = (float*)d_out;

    const int smem = 66 * WW * sizeof(float);     // 33792
    cudaFuncSetAttribute(decouple_kernel,
                         cudaFuncAttributeMaxDynamicSharedMemorySize, smem);

    pool_kernel<<<NB * CH, 256>>>(x, conv_w, gamma, beta, mean, var);

    cudaLaunchConfig_t cfg = {};
    cfg.gridDim  = dim3(NB * CH * 2, 1, 1);
    cfg.blockDim = dim3(256, 1, 1);
    cfg.dynamicSmemBytes = smem;
    cudaLaunchAttribute attrs[1];
    attrs[0].id = cudaLaunchAttributeProgrammaticStreamSerialization;
    attrs[0].val.programmaticStreamSerializationAllowed = 1;
    cfg.attrs = attrs;
    cfg.numAttrs = 1;
    cudaLaunchKernelEx(&cfg, decouple_kernel, x, out);
}

// round 5
// speedup vs baseline: 1.0400x; 1.0400x over previous
#include <cuda_runtime.h>
#include <cuda_bf16.h>
#include <math.h>

#define NB   16
#define CH   64
#define HH   128
#define WW   128
#define PLANE (HH*WW)          // 16384
#define GK2  72
#define BN_EPS 1e-5f

#define TROWS 32               // output rows per decouple CTA
#define HROWS (TROWS + 2)      // staged rows incl. halo

__device__ float g_pooled[NB * CH];
__device__ float g_f[NB * GK2];
__device__ int   g_cnt[NB];            // zero-init at load; self-resetting

// ---------------------------------------------------------------------------
// Kernel 1: avg-pool each plane; the LAST CTA of each image also computes the
// 72 BN+softmax weights for that image (no middle kernel launch).
// ---------------------------------------------------------------------------
__global__ void __launch_bounds__(256) pool_kernel(const float* __restrict__ x,
                                                   const float* __restrict__ conv_w,
                                                   const float* __restrict__ gamma,
                                                   const float* __restrict__ beta,
                                                   const float* __restrict__ mean,
                                                   const float* __restrict__ var) {
    const int p = blockIdx.x;                     // n*CH + c
    const int n = p >> 6;
    const float4* xp = (const float4*)(x + (size_t)p * PLANE);
    float s = 0.f;
    #pragma unroll
    for (int j = 0; j < 16; j++) {
        float4 v = xp[threadIdx.x + j * 256];
        s += (v.x + v.y) + (v.z + v.w);
    }
    #pragma unroll
    for (int o = 16; o > 0; o >>= 1) s += __shfl_xor_sync(0xffffffffu, s, o);

    __shared__ float ws[8];
    __shared__ int   is_last;
    __shared__ float sf[GK2];

    if ((threadIdx.x & 31) == 0) ws[threadIdx.x >> 5] = s;
    __syncthreads();
    if (threadIdx.x < 8) {
        s = ws[threadIdx.x];
        #pragma unroll
        for (int o = 4; o > 0; o >>= 1) s += __shfl_xor_sync(0x000000ffu, s, o);
        if (threadIdx.x == 0) {
            g_pooled[p] = s * (1.f / (float)PLANE);
            __threadfence();
            int old = atomicAdd(&g_cnt[n], 1);
            is_last = (old == CH - 1);
        }
    }
    __syncthreads();
    if (!is_last) return;

    __threadfence();                              // acquire g_pooled[n*64..]
    const int j = threadIdx.x;
    if (j < GK2) {
        const float* pn = g_pooled + n * CH;
        const float* wj = conv_w + j * CH;
        float acc = 0.f;
        #pragma unroll
        for (int c = 0; c < CH; c++) acc = fmaf(pn[c], wj[c], acc);
        acc = gamma[j] * (acc - mean[j]) * rsqrtf(var[j] + BN_EPS) + beta[j];
        sf[j] = acc;
    }
    __syncthreads();
    if (j < GK2) {
        const int g = j / 9;
        const float* sg = sf + g * 9;
        float m = sg[0];
        #pragma unroll
        for (int i = 1; i < 9; i++) m = fmaxf(m, sg[i]);
        float sum = 0.f;
        #pragma unroll
        for (int i = 0; i < 9; i++) sum += __expf(sg[i] - m);
        g_f[n * GK2 + j] = __expf(sf[j] - m) / sum;
    }
    if (j == 0) g_cnt[n] = 0;                     // reset for graph replay
}

// ---------------------------------------------------------------------------
// Kernel 2: 32-row tiles + 34-row staged halo (reflection baked into staging).
// Warp-per-row, conflict-free LDS.128 + lane shuffles; __stcs float4 stores.
// ---------------------------------------------------------------------------
__device__ __forceinline__ void row_taps(float4 v, int lane, float wl, float wc, float wr,
                                         float acc[4]) {
    float left  = __shfl_up_sync(0xffffffffu, v.w, 1);
    float right = __shfl_down_sync(0xffffffffu, v.x, 1);
    if (lane == 0)  left  = v.y;   // reflect x[-1] -> x[1]
    if (lane == 31) right = v.z;   // reflect x[128] -> x[126]
    acc[0] = fmaf(left, wl, fmaf(v.x, wc, fmaf(v.y, wr, acc[0])));
    acc[1] = fmaf(v.x,  wl, fmaf(v.y, wc, fmaf(v.z, wr, acc[1])));
    acc[2] = fmaf(v.y,  wl, fmaf(v.z, wc, fmaf(v.w, wr, acc[2])));
    acc[3] = fmaf(v.z,  wl, fmaf(v.w, wc, fmaf(right, wr, acc[3])));
}

__global__ void __launch_bounds__(256) decouple_kernel(const float* __restrict__ x,
                                                       float* __restrict__ out) {
    __shared__ float tile[HROWS * WW];            // 34*128*4 = 17408 B
    const int b = blockIdx.x;
    const int p = b >> 2;                         // plane
    const int start = (b & 3) * TROWS;            // first output row
    const size_t base = (size_t)p * PLANE;
    const float4* xin = (const float4*)(x + base);
    float4* t4 = (float4*)tile;

    // stage rows start-1 .. start+TROWS with top/bottom reflection applied
    #pragma unroll
    for (int j = 0; j < (HROWS * 32 + 255) / 256; j++) {
        const int i = threadIdx.x + j * 256;
        if (i < HROWS * 32) {
            int gr = start + (i >> 5) - 1;
            gr = (gr < 0) ? 1 : ((gr > HH - 1) ? HH - 2 : gr);
            t4[i] = xin[gr * 32 + (i & 31)];
        }
    }

    const int n = p >> 6;
    const int g = (p & 63) >> 3;
    const float* fw = g_f + n * GK2 + g * 9;
    float w[9];
    #pragma unroll
    for (int k = 0; k < 9; k++) w[k] = fw[k];
    __syncthreads();

    float4* olow = (float4*)(out + base);
    float4* ores = (float4*)(out + (size_t)NB * CH * PLANE + base);

    const int lane = threadIdx.x & 31;
    const int warp = threadIdx.x >> 5;            // 0..7

    #pragma unroll
    for (int iter = 0; iter < TROWS / 8; iter++) {
        const int tr = iter * 8 + warp + 1;       // tile row (center)
        float4 va = t4[(tr - 1) * 32 + lane];
        float4 vb = t4[ tr      * 32 + lane];
        float4 vc = t4[(tr + 1) * 32 + lane];

        float acc[4] = {0.f, 0.f, 0.f, 0.f};
        row_taps(va, lane, w[0], w[1], w[2], acc);
        row_taps(vb, lane, w[3], w[4], w[5], acc);
        row_taps(vc, lane, w[6], w[7], w[8], acc);

        float4 L = make_float4(acc[0], acc[1], acc[2], acc[3]);
        float4 R = make_float4(vb.x - acc[0], vb.y - acc[1],
                               vb.z - acc[2], vb.w - acc[3]);
        const int oi = (start + tr - 1) * 32 + lane;
        __stcs(olow + oi, L);
        __stcs(ores + oi, R);
    }
}

// ---------------------------------------------------------------------------
extern "C" void kernel_launch(void* const* d_in, const int* in_sizes, int n_in,
                              void* d_out, int out_size) {
    const float* x      = (const float*)d_in[0];
    const float* conv_w = (const float*)d_in[1];
    const float* gamma  = (const float*)d_in[2];
    const float* beta   = (const float*)d_in[3];
    const float* mean   = (const float*)d_in[4];
    const float* var    = (const float*)d_in[5];
    float* out = (float*)d_out;

    pool_kernel<<<NB * CH, 256>>>(x, conv_w, gamma, beta, mean, var);
    decouple_kernel<<<NB * CH * 4, 256>>>(x, out);
}